// round 12
// baseline (speedup 1.0000x reference)
#include <cuda_runtime.h>
#include <cuda_fp16.h>
#include <cstdint>

#define L_DIM 1024
#define N_DIM 4096
#define K_DIM 1024
#define NHEADS 4
#define NSCHUNK 8

// ---------------- scratch (device globals; no allocs allowed) ----------------
__device__ float g_q[L_DIM * N_DIM];
__device__ float g_keys[NHEADS * L_DIM * N_DIM];
__device__ float g_partial[NHEADS * NSCHUNK * N_DIM];
__device__ float g_weight[NHEADS * N_DIM];
__device__ float g_fused[L_DIM * N_DIM];

__device__ __half g_WL[L_DIM * K_DIM];
__device__ __half g_Wimg[NHEADS * L_DIM * K_DIM];
__device__ __half g_Wf[L_DIM * K_DIM];
__device__ __half g_PT[N_DIM * K_DIM];
__device__ __half g_IT[N_DIM * K_DIM];
__device__ __half g_FT[N_DIM * K_DIM];

// ---------------- PTX helpers (sm_80-portable only) ----------------
__device__ __forceinline__ uint32_t smem_u32(const void* p) {
    uint32_t r;
    asm("{ .reg .u64 t; cvta.to.shared.u64 t, %1; cvt.u32.u64 %0, t; }" : "=r"(r) : "l"(p));
    return r;
}
__device__ __forceinline__ void cp16(uint32_t dst, const void* src) {
    asm volatile("cp.async.cg.shared.global [%0], [%1], 16;" :: "r"(dst), "l"(src) : "memory");
}
__device__ __forceinline__ void cp_commit() {
    asm volatile("cp.async.commit_group;" ::: "memory");
}
__device__ __forceinline__ void cp_wait1() {
    asm volatile("cp.async.wait_group 1;" ::: "memory");
}
__device__ __forceinline__ void cp_wait0() {
    asm volatile("cp.async.wait_group 0;" ::: "memory");
}
__device__ __forceinline__ void ldsm_x4(uint32_t& r0, uint32_t& r1, uint32_t& r2, uint32_t& r3,
                                        uint32_t addr) {
    asm volatile("ldmatrix.sync.aligned.m8n8.x4.shared.b16 {%0,%1,%2,%3}, [%4];"
                 : "=r"(r0), "=r"(r1), "=r"(r2), "=r"(r3) : "r"(addr));
}
__device__ __forceinline__ void mma_f16(float* c, const uint32_t* a, uint32_t b0, uint32_t b1) {
    asm volatile(
        "mma.sync.aligned.m16n8k16.row.col.f32.f16.f16.f32 "
        "{%0,%1,%2,%3}, {%4,%5,%6,%7}, {%8,%9}, {%0,%1,%2,%3};"
        : "+f"(c[0]), "+f"(c[1]), "+f"(c[2]), "+f"(c[3])
        : "r"(a[0]), "r"(a[1]), "r"(a[2]), "r"(a[3]), "r"(b0), "r"(b1));
}

// ---------------- fp16 mma.sync GEMM: BM=128, BN=256, warp tile 64x64 ------------------
#define GBM 128
#define GBN 256
#define GBK 64
#define OFF_A 0
#define OFF_B 16384
#define STAGE_B 49152            // A 16KB + B 32KB
#define NSTAGE 3
#define GEMM_DSMEM (NSTAGE * STAGE_B)   // 144 KB -> 1 CTA/SM
#define KSTAGES (K_DIM / GBK)           // 16

template <bool SCORE>
__device__ __forceinline__ void gemm_body(
    const __half* __restrict__ A, const __half* __restrict__ B,
    const float* __restrict__ bias, float* __restrict__ C,
    int bm, int bn,
    const float* __restrict__ qbuf, float* __restrict__ partial, int chunk_idx)
{
    extern __shared__ char sm_raw[];
    const uint32_t sbase = smem_u32(sm_raw);

    const int tid  = threadIdx.x;
    const int lane = tid & 31;
    const int wid  = tid >> 5;
    const int wm   = wid >> 2;           // 0..1 (64 rows each)
    const int wn   = wid & 3;            // 0..3 (64 cols each)

    // cp.async mappings: A = 1024 16B-chunks (4/thread), B = 2048 (8/thread)
    uint32_t adst[4], bdst[8];
    int arow[4], acol[4], brow[8], bcol[8];
    #pragma unroll
    for (int t = 0; t < 4; t++) {
        int idx = (t << 8) + tid;
        int r = idx >> 3, c = idx & 7;
        arow[t] = r; acol[t] = c;
        adst[t] = (uint32_t)((r << 7) + ((c ^ (r & 7)) << 4));
    }
    #pragma unroll
    for (int t = 0; t < 8; t++) {
        int idx = (t << 8) + tid;
        int r = idx >> 3, c = idx & 7;
        brow[t] = r; bcol[t] = c;
        bdst[t] = (uint32_t)((r << 7) + ((c ^ (r & 7)) << 4));
    }

    auto issue_stage = [&](int kstage, int buf) {
        const uint32_t sb = sbase + buf * STAGE_B;
        const int k0 = kstage * GBK;
        #pragma unroll
        for (int t = 0; t < 4; t++)
            cp16(sb + OFF_A + adst[t],
                 A + (size_t)(bm + arow[t]) * K_DIM + k0 + (acol[t] << 3));
        #pragma unroll
        for (int t = 0; t < 8; t++)
            cp16(sb + OFF_B + bdst[t],
                 B + (size_t)(bn + brow[t]) * K_DIM + k0 + (bcol[t] << 3));
    };

    float acc[4][8][4];
    #pragma unroll
    for (int m = 0; m < 4; m++)
        #pragma unroll
        for (int n = 0; n < 8; n++)
            #pragma unroll
            for (int v = 0; v < 4; v++)
                acc[m][n][v] = 0.0f;

    const int a_row0 = wm * 64 + (lane & 15);
    const int a_ch0  = lane >> 4;
    const int b_row0 = wn * 64 + ((lane >> 4) << 3) + (lane & 7);
    const int b_ch0  = (lane >> 3) & 1;

    issue_stage(0, 0); cp_commit();
    issue_stage(1, 1); cp_commit();

    int bc = 0;
    for (int i = 0; i < KSTAGES; i++) {
        if (i < KSTAGES - 1) cp_wait1(); else cp_wait0();
        __syncthreads();

        if (i + 2 < KSTAGES) {
            int bi = bc + 2; if (bi >= NSTAGE) bi -= NSTAGE;
            issue_stage(i + 2, bi);
            cp_commit();
        }

        const uint32_t st = sbase + bc * STAGE_B;
        #pragma unroll
        for (int ks = 0; ks < 4; ks++) {
            uint32_t ah[4][4], bh[4][4];
            #pragma unroll
            for (int mt = 0; mt < 4; mt++) {
                const int r = a_row0 + mt * 16;
                const int ch = ks * 2 + a_ch0;
                ldsm_x4(ah[mt][0], ah[mt][1], ah[mt][2], ah[mt][3],
                        st + OFF_A + (r << 7) + ((ch ^ (r & 7)) << 4));
            }
            #pragma unroll
            for (int np = 0; np < 4; np++) {
                const int r = b_row0 + np * 16;
                const int ch = ks * 2 + b_ch0;
                ldsm_x4(bh[np][0], bh[np][1], bh[np][2], bh[np][3],
                        st + OFF_B + (r << 7) + ((ch ^ (r & 7)) << 4));
            }
            #pragma unroll
            for (int mt = 0; mt < 4; mt++)
                #pragma unroll
                for (int np = 0; np < 4; np++) {
                    mma_f16(acc[mt][np * 2 + 0], ah[mt], bh[np][0], bh[np][1]);
                    mma_f16(acc[mt][np * 2 + 1], ah[mt], bh[np][2], bh[np][3]);
                }
        }
        bc = (bc + 1 == NSTAGE) ? 0 : bc + 1;
    }

    float s[16];
    if (SCORE) {
        #pragma unroll
        for (int j = 0; j < 16; j++) s[j] = 0.0f;
    }

    #pragma unroll
    for (int mt = 0; mt < 4; mt++) {
        const int row = bm + wm * 64 + mt * 16 + (lane >> 2);
        const float bv0 = bias[row], bv8 = bias[row + 8];
        const int c0 = row & (L_DIM - 1);
        #pragma unroll
        for (int nt = 0; nt < 8; nt++) {
            const int col = bn + wn * 64 + nt * 8 + (lane & 3) * 2;
            const float k00 = acc[mt][nt][0] + bv0, k01 = acc[mt][nt][1] + bv0;
            const float k80 = acc[mt][nt][2] + bv8, k81 = acc[mt][nt][3] + bv8;
            *reinterpret_cast<float2*>(&C[(size_t)row * N_DIM + col]) =
                make_float2(k00, k01);
            *reinterpret_cast<float2*>(&C[(size_t)(row + 8) * N_DIM + col]) =
                make_float2(k80, k81);
            if (SCORE) {
                const float2 q0 = *reinterpret_cast<const float2*>(
                    &qbuf[(size_t)c0 * N_DIM + col]);
                const float2 q8 = *reinterpret_cast<const float2*>(
                    &qbuf[(size_t)(c0 + 8) * N_DIM + col]);
                s[nt * 2 + 0] += k00 * q0.x + k80 * q8.x;
                s[nt * 2 + 1] += k01 * q0.y + k81 * q8.y;
            }
        }
    }

    if (SCORE) {
        #pragma unroll
        for (int j = 0; j < 16; j++) {
            s[j] += __shfl_xor_sync(0xffffffffu, s[j], 4);
            s[j] += __shfl_xor_sync(0xffffffffu, s[j], 8);
            s[j] += __shfl_xor_sync(0xffffffffu, s[j], 16);
        }
        __syncthreads();
        float* sbuf = reinterpret_cast<float*>(sm_raw);   // [8 warps][64 cols]
        if ((lane >> 2) == 0) {
            #pragma unroll
            for (int nt = 0; nt < 8; nt++) {
                const int lc = nt * 8 + (lane & 3) * 2;
                sbuf[wid * 64 + lc + 0] = s[nt * 2 + 0];
                sbuf[wid * 64 + lc + 1] = s[nt * 2 + 1];
            }
        }
        __syncthreads();
        {
            const int c   = tid & 63;
            const int wn_ = tid >> 6;
            float tot = sbuf[wn_ * 64 + c] + sbuf[(wn_ + 4) * 64 + c];
            partial[(size_t)chunk_idx * N_DIM + bn + tid] = tot;
        }
    }
}

__global__ __launch_bounds__(256, 1) void gemm_q(
    const __half* __restrict__ WL, const __half* __restrict__ PT,
    const float* __restrict__ b_L, float* __restrict__ q)
{
    gemm_body<false>(WL, PT, b_L, q, blockIdx.y * GBM, blockIdx.x * GBN,
                     nullptr, nullptr, 0);
}

__global__ __launch_bounds__(256, 1) void gemm_keys(
    const __half* __restrict__ WI, const __half* __restrict__ IT,
    const float* __restrict__ b_img, float* __restrict__ keys,
    const float* __restrict__ q, float* __restrict__ partial)
{
    gemm_body<true>(WI, IT, b_img, keys, blockIdx.y * GBM, blockIdx.x * GBN,
                    q, partial, blockIdx.y);
}

__global__ __launch_bounds__(256, 1) void gemm_f(
    const __half* __restrict__ A, const __half* __restrict__ B,
    const float* __restrict__ bias, float* __restrict__ C)
{
    gemm_body<false>(A, B, bias, C, blockIdx.y * GBM, blockIdx.x * GBN,
                     nullptr, nullptr, 0);
}

// ---------------- fused weight convert (fp32 -> fp16, half2) ----------------
__global__ __launch_bounds__(256) void convert_w(
    const float* __restrict__ W_L, const float* __restrict__ W_img,
    const float* __restrict__ W_f,
    __half* __restrict__ WL, __half* __restrict__ WI, __half* __restrict__ WF)
{
    const int WSZ = L_DIM * K_DIM;
    int i = (blockIdx.x * 256 + threadIdx.x) * 2;
    const float* src; __half* dst; int off;
    if (i < WSZ)          { src = W_L;   dst = WL; off = i; }
    else if (i < 5 * WSZ) { src = W_img; dst = WI; off = i - WSZ; }
    else                  { src = W_f;   dst = WF; off = i - 5 * WSZ; }
    float2 v = *reinterpret_cast<const float2*>(src + off);
    *reinterpret_cast<__half2*>(dst + off) = __floats2half2_rn(v.x, v.y);
}

// ---------------- fp32 [K, N] -> fp16 [N, K] transpose ----------------
__global__ __launch_bounds__(256) void trans_h2(
    const float* __restrict__ X0, __half* __restrict__ T0,
    const float* __restrict__ X1, __half* __restrict__ T1)
{
    const float* X = (blockIdx.z == 0) ? X0 : X1;
    __half* Th = (blockIdx.z == 0) ? T0 : T1;
    __shared__ float t[32][33];
    int n0 = blockIdx.x * 32, k0 = blockIdx.y * 32;
    int tx = threadIdx.x & 31, ty = threadIdx.x >> 5;
    #pragma unroll
    for (int j = 0; j < 32; j += 8)
        t[ty + j][tx] = X[(size_t)(k0 + ty + j) * N_DIM + n0 + tx];
    __syncthreads();
    #pragma unroll
    for (int j = 0; j < 32; j += 8)
        Th[(size_t)(n0 + ty + j) * K_DIM + k0 + tx] = __float2half(t[tx][ty + j]);
}

__global__ __launch_bounds__(256) void trans_h1(
    const float* __restrict__ X, __half* __restrict__ Th)
{
    __shared__ float t[32][33];
    int n0 = blockIdx.x * 32, k0 = blockIdx.y * 32;
    int tx = threadIdx.x & 31, ty = threadIdx.x >> 5;
    #pragma unroll
    for (int j = 0; j < 32; j += 8)
        t[ty + j][tx] = X[(size_t)(k0 + ty + j) * N_DIM + n0 + tx];
    __syncthreads();
    #pragma unroll
    for (int j = 0; j < 32; j += 8)
        Th[(size_t)(n0 + ty + j) * K_DIM + k0 + tx] = __float2half(t[tx][ty + j]);
}

// ---------------- softmax over heads ----------------
__global__ __launch_bounds__(256) void softmax_heads(
    const float* __restrict__ partial, float* __restrict__ weight,
    float* __restrict__ wmap_out)
{
    int n = blockIdx.x * 256 + threadIdx.x;
    float s[NHEADS] = {0.f, 0.f, 0.f, 0.f};
    #pragma unroll
    for (int h = 0; h < NHEADS; h++)
        #pragma unroll
        for (int j = 0; j < NSCHUNK; j++)
            s[h] += partial[((size_t)(h * NSCHUNK + j)) * N_DIM + n];
    const float inv_sqrt_dk = 1.0f / 32.0f;
    float m = -1e30f;
    #pragma unroll
    for (int h = 0; h < NHEADS; h++) { s[h] *= inv_sqrt_dk; m = fmaxf(m, s[h]); }
    float e[NHEADS], sum = 0.f;
    #pragma unroll
    for (int h = 0; h < NHEADS; h++) { e[h] = __expf(s[h] - m); sum += e[h]; }
    float inv = 1.0f / sum;
    #pragma unroll
    for (int h = 0; h < NHEADS; h++) {
        float wv = e[h] * inv;
        weight[(size_t)h * N_DIM + n]   = wv;
        wmap_out[(size_t)h * N_DIM + n] = wv;
    }
}

// ---------------- z + residual + LayerNorm ----------------
__global__ __launch_bounds__(512) void z_layernorm(
    const float* __restrict__ keys, const float* __restrict__ q,
    const float* __restrict__ weight, const float* __restrict__ gamma,
    const float* __restrict__ beta, float* __restrict__ fused)
{
    const int c = blockIdx.x;
    __shared__ float r1[16], r2[16];
    __shared__ float s_mean, s_rstd;

    float v[2][4];
    float lsum = 0.f, lsq = 0.f;
    #pragma unroll
    for (int j = 0; j < 2; j++) {
        const int n4 = (j * 512 + threadIdx.x) * 4;
        float4 qa = *reinterpret_cast<const float4*>(&q[(size_t)c * N_DIM + n4]);
        v[j][0] = qa.x; v[j][1] = qa.y; v[j][2] = qa.z; v[j][3] = qa.w;
        #pragma unroll
        for (int h = 0; h < NHEADS; h++) {
            float4 kv = *reinterpret_cast<const float4*>(
                &keys[((size_t)(h * L_DIM + c)) * N_DIM + n4]);
            float4 wv = *reinterpret_cast<const float4*>(&weight[(size_t)h * N_DIM + n4]);
            v[j][0] += wv.x * kv.x; v[j][1] += wv.y * kv.y;
            v[j][2] += wv.z * kv.z; v[j][3] += wv.w * kv.w;
        }
        #pragma unroll
        for (int e = 0; e < 4; e++) { lsum += v[j][e]; lsq += v[j][e] * v[j][e]; }
    }
    #pragma unroll
    for (int o = 16; o > 0; o >>= 1) {
        lsum += __shfl_xor_sync(0xffffffffu, lsum, o);
        lsq  += __shfl_xor_sync(0xffffffffu, lsq, o);
    }
    const int wid = threadIdx.x >> 5, lid = threadIdx.x & 31;
    if (lid == 0) { r1[wid] = lsum; r2[wid] = lsq; }
    __syncthreads();
    if (threadIdx.x == 0) {
        float ts = 0.f, tq = 0.f;
        #pragma unroll
        for (int i = 0; i < 16; i++) { ts += r1[i]; tq += r2[i]; }
        float mean = ts * (1.0f / N_DIM);
        float var  = tq * (1.0f / N_DIM) - mean * mean;
        s_mean = mean;
        s_rstd = rsqrtf(var + 1e-5f);
    }
    __syncthreads();
    const float mean = s_mean, rstd = s_rstd;
    #pragma unroll
    for (int j = 0; j < 2; j++) {
        const int n4 = (j * 512 + threadIdx.x) * 4;
        float4 ga = *reinterpret_cast<const float4*>(&gamma[n4]);
        float4 ba = *reinterpret_cast<const float4*>(&beta[n4]);
        float4 o;
        o.x = (v[j][0] - mean) * rstd * ga.x + ba.x;
        o.y = (v[j][1] - mean) * rstd * ga.y + ba.y;
        o.z = (v[j][2] - mean) * rstd * ga.z + ba.z;
        o.w = (v[j][3] - mean) * rstd * ga.w + ba.w;
        *reinterpret_cast<float4*>(&fused[(size_t)c * N_DIM + n4]) = o;
    }
}

// ---------------- launch ----------------
extern "C" void kernel_launch(void* const* d_in, const int* in_sizes, int n_in,
                              void* d_out, int out_size)
{
    const float* point = (const float*)d_in[0];
    const float* img   = (const float*)d_in[1];
    const float* W_img = (const float*)d_in[2];
    const float* b_img = (const float*)d_in[3];
    const float* W_L   = (const float*)d_in[4];
    const float* b_L   = (const float*)d_in[5];
    const float* ln_g  = (const float*)d_in[6];
    const float* ln_b  = (const float*)d_in[7];
    const float* W_f   = (const float*)d_in[8];
    const float* b_f   = (const float*)d_in[9];

    float* out  = (float*)d_out;
    float* wmap = out + (size_t)L_DIM * N_DIM;

    float *q, *keys, *partial, *weight, *fused;
    cudaGetSymbolAddress((void**)&q,       g_q);
    cudaGetSymbolAddress((void**)&keys,    g_keys);
    cudaGetSymbolAddress((void**)&partial, g_partial);
    cudaGetSymbolAddress((void**)&weight,  g_weight);
    cudaGetSymbolAddress((void**)&fused,   g_fused);

    __half *WL, *WI, *WF, *PT, *IT, *FT;
    cudaGetSymbolAddress((void**)&WL, g_WL);
    cudaGetSymbolAddress((void**)&WI, g_Wimg);
    cudaGetSymbolAddress((void**)&WF, g_Wf);
    cudaGetSymbolAddress((void**)&PT, g_PT);
    cudaGetSymbolAddress((void**)&IT, g_IT);
    cudaGetSymbolAddress((void**)&FT, g_FT);

    cudaFuncSetAttribute(gemm_q,    cudaFuncAttributeMaxDynamicSharedMemorySize, GEMM_DSMEM);
    cudaFuncSetAttribute(gemm_keys, cudaFuncAttributeMaxDynamicSharedMemorySize, GEMM_DSMEM);
    cudaFuncSetAttribute(gemm_f,    cudaFuncAttributeMaxDynamicSharedMemorySize, GEMM_DSMEM);

    convert_w<<<(6 * L_DIM * K_DIM) / 512, 256>>>(W_L, W_img, W_f, WL, WI, WF);

    trans_h2<<<dim3(N_DIM / 32, K_DIM / 32, 2), 256>>>(point, PT, img, IT);

    gemm_q<<<dim3(N_DIM / GBN, L_DIM / GBM), 256, GEMM_DSMEM>>>(WL, PT, b_L, q);
    gemm_keys<<<dim3(N_DIM / GBN, (NHEADS * L_DIM) / GBM), 256, GEMM_DSMEM>>>(
        WI, IT, b_img, keys, q, partial);

    softmax_heads<<<N_DIM / 256, 256>>>(partial, weight, wmap);
    z_layernorm<<<L_DIM, 512>>>(keys, q, weight, ln_g, ln_b, fused);

    trans_h1<<<dim3(N_DIM / 32, K_DIM / 32), 256>>>(fused, FT);

    gemm_f<<<dim3(N_DIM / GBN, L_DIM / GBM), 256, GEMM_DSMEM>>>(WF, FT, b_f, out);
}

// round 13
// speedup vs baseline: 1.1410x; 1.1410x over previous
#include <cuda_runtime.h>
#include <cuda_fp16.h>
#include <cstdint>

#define L_DIM 1024
#define N_DIM 4096
#define K_DIM 1024
#define NHEADS 4
#define NSCHUNK 8

// ---------------- scratch (device globals; no allocs allowed) ----------------
__device__ float  g_q[L_DIM * N_DIM];
__device__ __half g_keysh[NHEADS * L_DIM * N_DIM];      // fp16 keys
__device__ float  g_partial[NHEADS * NSCHUNK * N_DIM];
__device__ float  g_weight[NHEADS * N_DIM];
__device__ __half g_fusedh[L_DIM * N_DIM];              // fp16 LN output [c,n]

__device__ __half g_WL[L_DIM * K_DIM];
__device__ __half g_Wimg[NHEADS * L_DIM * K_DIM];
__device__ __half g_Wf[L_DIM * K_DIM];
__device__ __half g_PT[N_DIM * K_DIM];
__device__ __half g_IT[N_DIM * K_DIM];
__device__ __half g_FT[N_DIM * K_DIM];

// ---------------- PTX helpers (sm_80-portable only) ----------------
__device__ __forceinline__ uint32_t smem_u32(const void* p) {
    uint32_t r;
    asm("{ .reg .u64 t; cvta.to.shared.u64 t, %1; cvt.u32.u64 %0, t; }" : "=r"(r) : "l"(p));
    return r;
}
__device__ __forceinline__ void cp16(uint32_t dst, const void* src) {
    asm volatile("cp.async.cg.shared.global [%0], [%1], 16;" :: "r"(dst), "l"(src) : "memory");
}
__device__ __forceinline__ void cp_commit() {
    asm volatile("cp.async.commit_group;" ::: "memory");
}
__device__ __forceinline__ void cp_wait1() {
    asm volatile("cp.async.wait_group 1;" ::: "memory");
}
__device__ __forceinline__ void cp_wait0() {
    asm volatile("cp.async.wait_group 0;" ::: "memory");
}
__device__ __forceinline__ void ldsm_x4(uint32_t& r0, uint32_t& r1, uint32_t& r2, uint32_t& r3,
                                        uint32_t addr) {
    asm volatile("ldmatrix.sync.aligned.m8n8.x4.shared.b16 {%0,%1,%2,%3}, [%4];"
                 : "=r"(r0), "=r"(r1), "=r"(r2), "=r"(r3) : "r"(addr));
}
__device__ __forceinline__ void mma_f16(float* c, const uint32_t* a, uint32_t b0, uint32_t b1) {
    asm volatile(
        "mma.sync.aligned.m16n8k16.row.col.f32.f16.f16.f32 "
        "{%0,%1,%2,%3}, {%4,%5,%6,%7}, {%8,%9}, {%0,%1,%2,%3};"
        : "+f"(c[0]), "+f"(c[1]), "+f"(c[2]), "+f"(c[3])
        : "r"(a[0]), "r"(a[1]), "r"(a[2]), "r"(a[3]), "r"(b0), "r"(b1));
}

// ---------------- fp16 mma.sync GEMM (R11 config: 32x64 warp tile, 2 CTAs/SM) ----------
#define GBM 128
#define GBN 128
#define GBK 64
#define OFF_A 0
#define OFF_B 16384
#define STAGE_B 32768
#define NSTAGE 3
#define GEMM_DSMEM (NSTAGE * STAGE_B)       // 96 KB -> 2 CTAs/SM
#define KSTAGES (K_DIM / GBK)               // 16

template <bool SCORE, typename OT>
__device__ __forceinline__ void gemm_body(
    const __half* __restrict__ A, const __half* __restrict__ B,
    const float* __restrict__ bias, OT* __restrict__ C,
    int bm, int bn,
    const float* __restrict__ qbuf, float* __restrict__ partial, int chunk_idx)
{
    extern __shared__ char sm_raw[];
    const uint32_t sbase = smem_u32(sm_raw);

    const int tid  = threadIdx.x;
    const int lane = tid & 31;
    const int wid  = tid >> 5;
    const int wm   = wid >> 1;
    const int wn   = wid & 1;

    int crow[4], ccol[4];
    uint32_t cdst[4];
    #pragma unroll
    for (int t = 0; t < 4; t++) {
        int idx = (t << 8) + tid;
        int r = idx >> 3, c = idx & 7;
        crow[t] = r; ccol[t] = c;
        cdst[t] = (uint32_t)((r << 7) + ((c ^ (r & 7)) << 4));
    }

    auto issue_stage = [&](int kstage, int buf) {
        const uint32_t sb = sbase + buf * STAGE_B;
        const int k0 = kstage * GBK;
        #pragma unroll
        for (int t = 0; t < 4; t++) {
            const int r = crow[t], c = ccol[t];
            cp16(sb + OFF_A + cdst[t], A + (size_t)(bm + r) * K_DIM + k0 + (c << 3));
            cp16(sb + OFF_B + cdst[t], B + (size_t)(bn + r) * K_DIM + k0 + (c << 3));
        }
    };

    float acc[2][8][4];
    #pragma unroll
    for (int m = 0; m < 2; m++)
        #pragma unroll
        for (int n = 0; n < 8; n++)
            #pragma unroll
            for (int v = 0; v < 4; v++)
                acc[m][n][v] = 0.0f;

    const int a_row0 = wm * 32 + (lane & 15);
    const int a_ch0  = lane >> 4;
    const int b_row0 = wn * 64 + ((lane >> 4) << 3) + (lane & 7);
    const int b_ch0  = (lane >> 3) & 1;

    issue_stage(0, 0); cp_commit();
    issue_stage(1, 1); cp_commit();

    int bc = 0;
    for (int i = 0; i < KSTAGES; i++) {
        if (i < KSTAGES - 1) cp_wait1(); else cp_wait0();
        __syncthreads();

        if (i + 2 < KSTAGES) {
            int bi = bc + 2; if (bi >= NSTAGE) bi -= NSTAGE;
            issue_stage(i + 2, bi);
            cp_commit();
        }

        const uint32_t st = sbase + bc * STAGE_B;
        #pragma unroll
        for (int ks = 0; ks < 4; ks++) {
            uint32_t ah[2][4], bh[4][4];
            #pragma unroll
            for (int mt = 0; mt < 2; mt++) {
                const int r = a_row0 + mt * 16;
                const int ch = ks * 2 + a_ch0;
                ldsm_x4(ah[mt][0], ah[mt][1], ah[mt][2], ah[mt][3],
                        st + OFF_A + (r << 7) + ((ch ^ (r & 7)) << 4));
            }
            #pragma unroll
            for (int np = 0; np < 4; np++) {
                const int r = b_row0 + np * 16;
                const int ch = ks * 2 + b_ch0;
                ldsm_x4(bh[np][0], bh[np][1], bh[np][2], bh[np][3],
                        st + OFF_B + (r << 7) + ((ch ^ (r & 7)) << 4));
            }
            #pragma unroll
            for (int mt = 0; mt < 2; mt++)
                #pragma unroll
                for (int np = 0; np < 4; np++) {
                    mma_f16(acc[mt][np * 2 + 0], ah[mt], bh[np][0], bh[np][1]);
                    mma_f16(acc[mt][np * 2 + 1], ah[mt], bh[np][2], bh[np][3]);
                }
        }
        bc = (bc + 1 == NSTAGE) ? 0 : bc + 1;
    }

    float s[16];
    if (SCORE) {
        #pragma unroll
        for (int j = 0; j < 16; j++) s[j] = 0.0f;
    }

    #pragma unroll
    for (int mt = 0; mt < 2; mt++) {
        const int row = bm + wm * 32 + mt * 16 + (lane >> 2);
        const float bv0 = bias[row], bv8 = bias[row + 8];
        const int c0 = row & (L_DIM - 1);
        #pragma unroll
        for (int nt = 0; nt < 8; nt++) {
            const int col = bn + wn * 64 + nt * 8 + (lane & 3) * 2;
            const float k00 = acc[mt][nt][0] + bv0, k01 = acc[mt][nt][1] + bv0;
            const float k80 = acc[mt][nt][2] + bv8, k81 = acc[mt][nt][3] + bv8;
            if (sizeof(OT) == 2) {
                *reinterpret_cast<__half2*>(
                    (__half*)C + (size_t)row * N_DIM + col) = __floats2half2_rn(k00, k01);
                *reinterpret_cast<__half2*>(
                    (__half*)C + (size_t)(row + 8) * N_DIM + col) = __floats2half2_rn(k80, k81);
            } else {
                *reinterpret_cast<float2*>(
                    (float*)C + (size_t)row * N_DIM + col) = make_float2(k00, k01);
                *reinterpret_cast<float2*>(
                    (float*)C + (size_t)(row + 8) * N_DIM + col) = make_float2(k80, k81);
            }
            if (SCORE) {
                const float2 q0 = *reinterpret_cast<const float2*>(
                    &qbuf[(size_t)c0 * N_DIM + col]);
                const float2 q8 = *reinterpret_cast<const float2*>(
                    &qbuf[(size_t)(c0 + 8) * N_DIM + col]);
                s[nt * 2 + 0] += k00 * q0.x + k80 * q8.x;
                s[nt * 2 + 1] += k01 * q0.y + k81 * q8.y;
            }
        }
    }

    if (SCORE) {
        #pragma unroll
        for (int j = 0; j < 16; j++) {
            s[j] += __shfl_xor_sync(0xffffffffu, s[j], 4);
            s[j] += __shfl_xor_sync(0xffffffffu, s[j], 8);
            s[j] += __shfl_xor_sync(0xffffffffu, s[j], 16);
        }
        __syncthreads();
        float* sbuf = reinterpret_cast<float*>(sm_raw);   // [8 warps][128 cols]
        if ((lane >> 2) == 0) {
            #pragma unroll
            for (int nt = 0; nt < 8; nt++) {
                const int lc = wn * 64 + nt * 8 + (lane & 3) * 2;
                sbuf[wid * 128 + lc + 0] = s[nt * 2 + 0];
                sbuf[wid * 128 + lc + 1] = s[nt * 2 + 1];
            }
        }
        __syncthreads();
        if (tid < 128) {
            const int wn_ = tid >> 6;
            float tot = sbuf[(0 * 2 + wn_) * 128 + tid]
                      + sbuf[(1 * 2 + wn_) * 128 + tid]
                      + sbuf[(2 * 2 + wn_) * 128 + tid]
                      + sbuf[(3 * 2 + wn_) * 128 + tid];
            partial[(size_t)chunk_idx * N_DIM + bn + tid] = tot;
        }
    }
}

__global__ __launch_bounds__(256, 2) void gemm_q(
    const __half* __restrict__ WL, const __half* __restrict__ PT,
    const float* __restrict__ b_L, float* __restrict__ q)
{
    gemm_body<false, float>(WL, PT, b_L, q, blockIdx.y * GBM, blockIdx.x * GBN,
                            nullptr, nullptr, 0);
}

__global__ __launch_bounds__(256, 2) void gemm_keys(
    const __half* __restrict__ WI, const __half* __restrict__ IT,
    const float* __restrict__ b_img, __half* __restrict__ keysh,
    const float* __restrict__ q, float* __restrict__ partial)
{
    gemm_body<true, __half>(WI, IT, b_img, keysh, blockIdx.y * GBM, blockIdx.x * GBN,
                            q, partial, blockIdx.y);
}

__global__ __launch_bounds__(256, 2) void gemm_f(
    const __half* __restrict__ A, const __half* __restrict__ B,
    const float* __restrict__ bias, float* __restrict__ C)
{
    gemm_body<false, float>(A, B, bias, C, blockIdx.y * GBM, blockIdx.x * GBN,
                            nullptr, nullptr, 0);
}

// ---------------- fused weight convert (fp32 -> fp16, half2) ----------------
__global__ __launch_bounds__(256) void convert_w(
    const float* __restrict__ W_L, const float* __restrict__ W_img,
    const float* __restrict__ W_f,
    __half* __restrict__ WL, __half* __restrict__ WI, __half* __restrict__ WF)
{
    const int WSZ = L_DIM * K_DIM;
    int i = (blockIdx.x * 256 + threadIdx.x) * 2;
    const float* src; __half* dst; int off;
    if (i < WSZ)          { src = W_L;   dst = WL; off = i; }
    else if (i < 5 * WSZ) { src = W_img; dst = WI; off = i - WSZ; }
    else                  { src = W_f;   dst = WF; off = i - 5 * WSZ; }
    float2 v = *reinterpret_cast<const float2*>(src + off);
    *reinterpret_cast<__half2*>(dst + off) = __floats2half2_rn(v.x, v.y);
}

// ---------------- fp32 [K, N] -> fp16 [N, K] transpose (inputs) ----------------
__global__ __launch_bounds__(256) void trans_h2(
    const float* __restrict__ X0, __half* __restrict__ T0,
    const float* __restrict__ X1, __half* __restrict__ T1)
{
    const float* X = (blockIdx.z == 0) ? X0 : X1;
    __half* Th = (blockIdx.z == 0) ? T0 : T1;
    __shared__ float t[32][33];
    int n0 = blockIdx.x * 32, k0 = blockIdx.y * 32;
    int tx = threadIdx.x & 31, ty = threadIdx.x >> 5;
    #pragma unroll
    for (int j = 0; j < 32; j += 8)
        t[ty + j][tx] = X[(size_t)(k0 + ty + j) * N_DIM + n0 + tx];
    __syncthreads();
    #pragma unroll
    for (int j = 0; j < 32; j += 8)
        Th[(size_t)(n0 + ty + j) * K_DIM + k0 + tx] = __float2half(t[tx][ty + j]);
}

// ---------------- fp16 [K, N] -> fp16 [N, K] transpose (fused) ----------------
__global__ __launch_bounds__(256) void trans_h1h(
    const __half* __restrict__ X, __half* __restrict__ Th)
{
    __shared__ __half t[32][34];
    int n0 = blockIdx.x * 32, k0 = blockIdx.y * 32;
    int tx = threadIdx.x & 31, ty = threadIdx.x >> 5;
    #pragma unroll
    for (int j = 0; j < 32; j += 8)
        t[ty + j][tx] = X[(size_t)(k0 + ty + j) * N_DIM + n0 + tx];
    __syncthreads();
    #pragma unroll
    for (int j = 0; j < 32; j += 8)
        Th[(size_t)(n0 + ty + j) * K_DIM + k0 + tx] = t[tx][ty + j];
}

// ---------------- softmax over heads ----------------
__global__ __launch_bounds__(256) void softmax_heads(
    const float* __restrict__ partial, float* __restrict__ weight,
    float* __restrict__ wmap_out)
{
    int n = blockIdx.x * 256 + threadIdx.x;
    float s[NHEADS] = {0.f, 0.f, 0.f, 0.f};
    #pragma unroll
    for (int h = 0; h < NHEADS; h++)
        #pragma unroll
        for (int j = 0; j < NSCHUNK; j++)
            s[h] += partial[((size_t)(h * NSCHUNK + j)) * N_DIM + n];
    const float inv_sqrt_dk = 1.0f / 32.0f;
    float m = -1e30f;
    #pragma unroll
    for (int h = 0; h < NHEADS; h++) { s[h] *= inv_sqrt_dk; m = fmaxf(m, s[h]); }
    float e[NHEADS], sum = 0.f;
    #pragma unroll
    for (int h = 0; h < NHEADS; h++) { e[h] = __expf(s[h] - m); sum += e[h]; }
    float inv = 1.0f / sum;
    #pragma unroll
    for (int h = 0; h < NHEADS; h++) {
        float wv = e[h] * inv;
        weight[(size_t)h * N_DIM + n]   = wv;
        wmap_out[(size_t)h * N_DIM + n] = wv;
    }
}

// ---------------- z + residual + LayerNorm (fp16 keys in, fp16 fused out) -------------
__global__ __launch_bounds__(512) void z_layernorm(
    const __half* __restrict__ keysh, const float* __restrict__ q,
    const float* __restrict__ weight, const float* __restrict__ gamma,
    const float* __restrict__ beta, __half* __restrict__ fusedh)
{
    const int c = blockIdx.x;
    __shared__ float r1[16], r2[16];
    __shared__ float s_mean, s_rstd;

    float v[2][4];
    float lsum = 0.f, lsq = 0.f;
    #pragma unroll
    for (int j = 0; j < 2; j++) {
        const int n4 = (j * 512 + threadIdx.x) * 4;
        float4 qa = *reinterpret_cast<const float4*>(&q[(size_t)c * N_DIM + n4]);
        v[j][0] = qa.x; v[j][1] = qa.y; v[j][2] = qa.z; v[j][3] = qa.w;
        #pragma unroll
        for (int h = 0; h < NHEADS; h++) {
            const __half2* kh = reinterpret_cast<const __half2*>(
                &keysh[((size_t)(h * L_DIM + c)) * N_DIM + n4]);
            float2 ka = __half22float2(kh[0]);
            float2 kb = __half22float2(kh[1]);
            float4 wv = *reinterpret_cast<const float4*>(&weight[(size_t)h * N_DIM + n4]);
            v[j][0] += wv.x * ka.x; v[j][1] += wv.y * ka.y;
            v[j][2] += wv.z * kb.x; v[j][3] += wv.w * kb.y;
        }
        #pragma unroll
        for (int e = 0; e < 4; e++) { lsum += v[j][e]; lsq += v[j][e] * v[j][e]; }
    }
    #pragma unroll
    for (int o = 16; o > 0; o >>= 1) {
        lsum += __shfl_xor_sync(0xffffffffu, lsum, o);
        lsq  += __shfl_xor_sync(0xffffffffu, lsq, o);
    }
    const int wid = threadIdx.x >> 5, lid = threadIdx.x & 31;
    if (lid == 0) { r1[wid] = lsum; r2[wid] = lsq; }
    __syncthreads();
    if (threadIdx.x == 0) {
        float ts = 0.f, tq = 0.f;
        #pragma unroll
        for (int i = 0; i < 16; i++) { ts += r1[i]; tq += r2[i]; }
        float mean = ts * (1.0f / N_DIM);
        float var  = tq * (1.0f / N_DIM) - mean * mean;
        s_mean = mean;
        s_rstd = rsqrtf(var + 1e-5f);
    }
    __syncthreads();
    const float mean = s_mean, rstd = s_rstd;
    #pragma unroll
    for (int j = 0; j < 2; j++) {
        const int n4 = (j * 512 + threadIdx.x) * 4;
        float4 ga = *reinterpret_cast<const float4*>(&gamma[n4]);
        float4 ba = *reinterpret_cast<const float4*>(&beta[n4]);
        float o0 = (v[j][0] - mean) * rstd * ga.x + ba.x;
        float o1 = (v[j][1] - mean) * rstd * ga.y + ba.y;
        float o2 = (v[j][2] - mean) * rstd * ga.z + ba.z;
        float o3 = (v[j][3] - mean) * rstd * ga.w + ba.w;
        __half2* dst = reinterpret_cast<__half2*>(&fusedh[(size_t)c * N_DIM + n4]);
        dst[0] = __floats2half2_rn(o0, o1);
        dst[1] = __floats2half2_rn(o2, o3);
    }
}

// ---------------- launch ----------------
extern "C" void kernel_launch(void* const* d_in, const int* in_sizes, int n_in,
                              void* d_out, int out_size)
{
    const float* point = (const float*)d_in[0];
    const float* img   = (const float*)d_in[1];
    const float* W_img = (const float*)d_in[2];
    const float* b_img = (const float*)d_in[3];
    const float* W_L   = (const float*)d_in[4];
    const float* b_L   = (const float*)d_in[5];
    const float* ln_g  = (const float*)d_in[6];
    const float* ln_b  = (const float*)d_in[7];
    const float* W_f   = (const float*)d_in[8];
    const float* b_f   = (const float*)d_in[9];

    float* out  = (float*)d_out;
    float* wmap = out + (size_t)L_DIM * N_DIM;

    float *q, *partial, *weight;
    __half *keysh, *fusedh;
    cudaGetSymbolAddress((void**)&q,       g_q);
    cudaGetSymbolAddress((void**)&keysh,   g_keysh);
    cudaGetSymbolAddress((void**)&partial, g_partial);
    cudaGetSymbolAddress((void**)&weight,  g_weight);
    cudaGetSymbolAddress((void**)&fusedh,  g_fusedh);

    __half *WL, *WI, *WF, *PT, *IT, *FT;
    cudaGetSymbolAddress((void**)&WL, g_WL);
    cudaGetSymbolAddress((void**)&WI, g_Wimg);
    cudaGetSymbolAddress((void**)&WF, g_Wf);
    cudaGetSymbolAddress((void**)&PT, g_PT);
    cudaGetSymbolAddress((void**)&IT, g_IT);
    cudaGetSymbolAddress((void**)&FT, g_FT);

    cudaFuncSetAttribute(gemm_q,    cudaFuncAttributeMaxDynamicSharedMemorySize, GEMM_DSMEM);
    cudaFuncSetAttribute(gemm_keys, cudaFuncAttributeMaxDynamicSharedMemorySize, GEMM_DSMEM);
    cudaFuncSetAttribute(gemm_f,    cudaFuncAttributeMaxDynamicSharedMemorySize, GEMM_DSMEM);

    convert_w<<<(6 * L_DIM * K_DIM) / 512, 256>>>(W_L, W_img, W_f, WL, WI, WF);

    trans_h2<<<dim3(N_DIM / 32, K_DIM / 32, 2), 256>>>(point, PT, img, IT);

    gemm_q<<<dim3(N_DIM / GBN, L_DIM / GBM), 256, GEMM_DSMEM>>>(WL, PT, b_L, q);
    gemm_keys<<<dim3(N_DIM / GBN, (NHEADS * L_DIM) / GBM), 256, GEMM_DSMEM>>>(
        WI, IT, b_img, keysh, q, partial);

    softmax_heads<<<N_DIM / 256, 256>>>(partial, weight, wmap);
    z_layernorm<<<L_DIM, 512>>>(keysh, q, weight, ln_g, ln_b, fusedh);

    trans_h1h<<<dim3(N_DIM / 32, K_DIM / 32), 256>>>(fusedh, FT);

    gemm_f<<<dim3(N_DIM / GBN, L_DIM / GBM), 256, GEMM_DSMEM>>>(WF, FT, b_f, out);
}

// round 14
// speedup vs baseline: 1.1881x; 1.0413x over previous
#include <cuda_runtime.h>
#include <cuda_fp16.h>
#include <cstdint>

#define L_DIM 1024
#define N_DIM 4096
#define K_DIM 1024
#define NHEADS 4
#define NSCHUNK 8

// ---------------- scratch (device globals; no allocs allowed) ----------------
__device__ float  g_q[L_DIM * N_DIM];
__device__ __half g_keysh[NHEADS * L_DIM * N_DIM];
__device__ float  g_partial[NHEADS * NSCHUNK * N_DIM];
__device__ float  g_weight[NHEADS * N_DIM];
__device__ __half g_fusedh[L_DIM * N_DIM];              // fp16 LN out [k,n] -> B of gemm_f

__device__ __half g_WL[L_DIM * K_DIM];
__device__ __half g_Wimg[NHEADS * L_DIM * K_DIM];
__device__ __half g_Wf[L_DIM * K_DIM];
__device__ __half g_P16[K_DIM * N_DIM];                 // point fp16 [k,n]
__device__ __half g_I16[K_DIM * N_DIM];                 // img   fp16 [k,n]

// ---------------- PTX helpers (sm_80-portable only) ----------------
__device__ __forceinline__ uint32_t smem_u32(const void* p) {
    uint32_t r;
    asm("{ .reg .u64 t; cvta.to.shared.u64 t, %1; cvt.u32.u64 %0, t; }" : "=r"(r) : "l"(p));
    return r;
}
__device__ __forceinline__ void cp16(uint32_t dst, const void* src) {
    asm volatile("cp.async.cg.shared.global [%0], [%1], 16;" :: "r"(dst), "l"(src) : "memory");
}
__device__ __forceinline__ void cp_commit() {
    asm volatile("cp.async.commit_group;" ::: "memory");
}
__device__ __forceinline__ void cp_wait1() {
    asm volatile("cp.async.wait_group 1;" ::: "memory");
}
__device__ __forceinline__ void cp_wait0() {
    asm volatile("cp.async.wait_group 0;" ::: "memory");
}
__device__ __forceinline__ void ldsm_x4(uint32_t& r0, uint32_t& r1, uint32_t& r2, uint32_t& r3,
                                        uint32_t addr) {
    asm volatile("ldmatrix.sync.aligned.m8n8.x4.shared.b16 {%0,%1,%2,%3}, [%4];"
                 : "=r"(r0), "=r"(r1), "=r"(r2), "=r"(r3) : "r"(addr));
}
__device__ __forceinline__ void ldsm_x4_trans(uint32_t& r0, uint32_t& r1, uint32_t& r2, uint32_t& r3,
                                              uint32_t addr) {
    asm volatile("ldmatrix.sync.aligned.m8n8.x4.trans.shared.b16 {%0,%1,%2,%3}, [%4];"
                 : "=r"(r0), "=r"(r1), "=r"(r2), "=r"(r3) : "r"(addr));
}
__device__ __forceinline__ void mma_f16(float* c, const uint32_t* a, uint32_t b0, uint32_t b1) {
    asm volatile(
        "mma.sync.aligned.m16n8k16.row.col.f32.f16.f16.f32 "
        "{%0,%1,%2,%3}, {%4,%5,%6,%7}, {%8,%9}, {%0,%1,%2,%3};"
        : "+f"(c[0]), "+f"(c[1]), "+f"(c[2]), "+f"(c[3])
        : "r"(a[0]), "r"(a[1]), "r"(a[2]), "r"(a[3]), "r"(b0), "r"(b1));
}

// ---------------- fp16 mma.sync GEMM: A [m,k] k-major, B [k,n] n-major (ldsm.trans) ----
#define GBM 128
#define GBN 128
#define GBK 64
#define OFF_A 0
#define OFF_B 16384
#define STAGE_B 32768           // A 16KB + B 16KB
#define NSTAGE 3
#define GEMM_DSMEM (NSTAGE * STAGE_B)   // 96 KB -> 2 CTAs/SM
#define KSTAGES (K_DIM / GBK)           // 16

template <bool SCORE, typename OT>
__device__ __forceinline__ void gemm_body(
    const __half* __restrict__ A, const __half* __restrict__ B,
    const float* __restrict__ bias, OT* __restrict__ C,
    int bm, int bn,
    const float* __restrict__ qbuf, float* __restrict__ partial, int chunk_idx)
{
    extern __shared__ char sm_raw[];
    const uint32_t sbase = smem_u32(sm_raw);

    const int tid  = threadIdx.x;
    const int lane = tid & 31;
    const int wid  = tid >> 5;
    const int wm   = wid >> 1;
    const int wn   = wid & 1;

    // A cp mapping: 128 rows x 8 chunks (16B). B cp mapping: 64 rows x 16 chunks.
    int arow[4], acol[4], brow[4], bcol[4];
    uint32_t adst[4], bdst[4];
    #pragma unroll
    for (int t = 0; t < 4; t++) {
        int idx = (t << 8) + tid;
        int ra = idx >> 3, ca = idx & 7;
        arow[t] = ra; acol[t] = ca;
        adst[t] = (uint32_t)((ra << 7) + ((ca ^ (ra & 7)) << 4));
        int rb = idx >> 4, cb = idx & 15;
        brow[t] = rb; bcol[t] = cb;
        bdst[t] = (uint32_t)((rb << 8) + ((cb ^ (rb & 7)) << 4));
    }

    auto issue_stage = [&](int kstage, int buf) {
        const uint32_t sb = sbase + buf * STAGE_B;
        const int k0 = kstage * GBK;
        #pragma unroll
        for (int t = 0; t < 4; t++) {
            cp16(sb + OFF_A + adst[t],
                 A + (size_t)(bm + arow[t]) * K_DIM + k0 + (acol[t] << 3));
            cp16(sb + OFF_B + bdst[t],
                 B + (size_t)(k0 + brow[t]) * N_DIM + bn + (bcol[t] << 3));
        }
    };

    float acc[2][8][4];
    #pragma unroll
    for (int m = 0; m < 2; m++)
        #pragma unroll
        for (int n = 0; n < 8; n++)
            #pragma unroll
            for (int v = 0; v < 4; v++)
                acc[m][n][v] = 0.0f;

    const int a_row0 = wm * 32 + (lane & 15);
    const int a_ch0  = lane >> 4;
    // B (ldsm.trans from [k,n]): k-local row + n-chunk
    const int b_krow0 = (lane & 7) + (((lane >> 3) & 1) << 3);   // 0..15
    const int b_nch0  = wn * 8 + (lane >> 4);                    // +np*2

    issue_stage(0, 0); cp_commit();
    issue_stage(1, 1); cp_commit();

    int bc = 0;
    for (int i = 0; i < KSTAGES; i++) {
        if (i < KSTAGES - 1) cp_wait1(); else cp_wait0();
        __syncthreads();

        if (i + 2 < KSTAGES) {
            int bi = bc + 2; if (bi >= NSTAGE) bi -= NSTAGE;
            issue_stage(i + 2, bi);
            cp_commit();
        }

        const uint32_t st = sbase + bc * STAGE_B;
        #pragma unroll
        for (int ks = 0; ks < 4; ks++) {
            uint32_t ah[2][4], bh[4][4];
            #pragma unroll
            for (int mt = 0; mt < 2; mt++) {
                const int r = a_row0 + mt * 16;
                const int ch = ks * 2 + a_ch0;
                ldsm_x4(ah[mt][0], ah[mt][1], ah[mt][2], ah[mt][3],
                        st + OFF_A + (r << 7) + ((ch ^ (r & 7)) << 4));
            }
            #pragma unroll
            for (int np = 0; np < 4; np++) {
                const int r = ks * 16 + b_krow0;
                const int nc = b_nch0 + np * 2;
                ldsm_x4_trans(bh[np][0], bh[np][1], bh[np][2], bh[np][3],
                              st + OFF_B + (r << 8) + ((nc ^ (r & 7)) << 4));
            }
            #pragma unroll
            for (int mt = 0; mt < 2; mt++)
                #pragma unroll
                for (int np = 0; np < 4; np++) {
                    mma_f16(acc[mt][np * 2 + 0], ah[mt], bh[np][0], bh[np][1]);
                    mma_f16(acc[mt][np * 2 + 1], ah[mt], bh[np][2], bh[np][3]);
                }
        }
        bc = (bc + 1 == NSTAGE) ? 0 : bc + 1;
    }

    float s[16];
    if (SCORE) {
        #pragma unroll
        for (int j = 0; j < 16; j++) s[j] = 0.0f;
    }

    #pragma unroll
    for (int mt = 0; mt < 2; mt++) {
        const int row = bm + wm * 32 + mt * 16 + (lane >> 2);
        const float bv0 = bias[row], bv8 = bias[row + 8];
        const int c0 = row & (L_DIM - 1);
        #pragma unroll
        for (int nt = 0; nt < 8; nt++) {
            const int col = bn + wn * 64 + nt * 8 + (lane & 3) * 2;
            const float k00 = acc[mt][nt][0] + bv0, k01 = acc[mt][nt][1] + bv0;
            const float k80 = acc[mt][nt][2] + bv8, k81 = acc[mt][nt][3] + bv8;
            if (sizeof(OT) == 2) {
                *reinterpret_cast<__half2*>(
                    (__half*)C + (size_t)row * N_DIM + col) = __floats2half2_rn(k00, k01);
                *reinterpret_cast<__half2*>(
                    (__half*)C + (size_t)(row + 8) * N_DIM + col) = __floats2half2_rn(k80, k81);
            } else {
                *reinterpret_cast<float2*>(
                    (float*)C + (size_t)row * N_DIM + col) = make_float2(k00, k01);
                *reinterpret_cast<float2*>(
                    (float*)C + (size_t)(row + 8) * N_DIM + col) = make_float2(k80, k81);
            }
            if (SCORE) {
                const float2 q0 = *reinterpret_cast<const float2*>(
                    &qbuf[(size_t)c0 * N_DIM + col]);
                const float2 q8 = *reinterpret_cast<const float2*>(
                    &qbuf[(size_t)(c0 + 8) * N_DIM + col]);
                s[nt * 2 + 0] += k00 * q0.x + k80 * q8.x;
                s[nt * 2 + 1] += k01 * q0.y + k81 * q8.y;
            }
        }
    }

    if (SCORE) {
        #pragma unroll
        for (int j = 0; j < 16; j++) {
            s[j] += __shfl_xor_sync(0xffffffffu, s[j], 4);
            s[j] += __shfl_xor_sync(0xffffffffu, s[j], 8);
            s[j] += __shfl_xor_sync(0xffffffffu, s[j], 16);
        }
        __syncthreads();
        float* sbuf = reinterpret_cast<float*>(sm_raw);
        if ((lane >> 2) == 0) {
            #pragma unroll
            for (int nt = 0; nt < 8; nt++) {
                const int lc = wn * 64 + nt * 8 + (lane & 3) * 2;
                sbuf[wid * 128 + lc + 0] = s[nt * 2 + 0];
                sbuf[wid * 128 + lc + 1] = s[nt * 2 + 1];
            }
        }
        __syncthreads();
        if (tid < 128) {
            const int wn_ = tid >> 6;
            float tot = sbuf[(0 * 2 + wn_) * 128 + tid]
                      + sbuf[(1 * 2 + wn_) * 128 + tid]
                      + sbuf[(2 * 2 + wn_) * 128 + tid]
                      + sbuf[(3 * 2 + wn_) * 128 + tid];
            partial[(size_t)chunk_idx * N_DIM + bn + tid] = tot;
        }
    }
}

__global__ __launch_bounds__(256, 2) void gemm_q(
    const __half* __restrict__ WL, const __half* __restrict__ P16,
    const float* __restrict__ b_L, float* __restrict__ q)
{
    gemm_body<false, float>(WL, P16, b_L, q, blockIdx.y * GBM, blockIdx.x * GBN,
                            nullptr, nullptr, 0);
}

__global__ __launch_bounds__(256, 2) void gemm_keys(
    const __half* __restrict__ WI, const __half* __restrict__ I16,
    const float* __restrict__ b_img, __half* __restrict__ keysh,
    const float* __restrict__ q, float* __restrict__ partial)
{
    gemm_body<true, __half>(WI, I16, b_img, keysh, blockIdx.y * GBM, blockIdx.x * GBN,
                            q, partial, blockIdx.y);
}

__global__ __launch_bounds__(256, 2) void gemm_f(
    const __half* __restrict__ WF, const __half* __restrict__ F16,
    const float* __restrict__ bias, float* __restrict__ C)
{
    gemm_body<false, float>(WF, F16, bias, C, blockIdx.y * GBM, blockIdx.x * GBN,
                            nullptr, nullptr, 0);
}

// ---------------- fused weight convert (fp32 -> fp16, half2) ----------------
__global__ __launch_bounds__(256) void convert_w(
    const float* __restrict__ W_L, const float* __restrict__ W_img,
    const float* __restrict__ W_f,
    __half* __restrict__ WL, __half* __restrict__ WI, __half* __restrict__ WF)
{
    const int WSZ = L_DIM * K_DIM;
    int i = (blockIdx.x * 256 + threadIdx.x) * 2;
    const float* src; __half* dst; int off;
    if (i < WSZ)          { src = W_L;   dst = WL; off = i; }
    else if (i < 5 * WSZ) { src = W_img; dst = WI; off = i - WSZ; }
    else                  { src = W_f;   dst = WF; off = i - 5 * WSZ; }
    float2 v = *reinterpret_cast<const float2*>(src + off);
    *reinterpret_cast<__half2*>(dst + off) = __floats2half2_rn(v.x, v.y);
}

// ---------------- activation convert: fp32 [k,n] -> fp16 [k,n] ----------------
__global__ __launch_bounds__(256) void convert_act(
    const float* __restrict__ X0, __half* __restrict__ T0,
    const float* __restrict__ X1, __half* __restrict__ T1)
{
    const float* X = (blockIdx.y == 0) ? X0 : X1;
    __half* T = (blockIdx.y == 0) ? T0 : T1;
    size_t i = ((size_t)blockIdx.x * 256 + threadIdx.x) * 4;
    float4 v = *reinterpret_cast<const float4*>(X + i);
    __half2* d = reinterpret_cast<__half2*>(T + i);
    d[0] = __floats2half2_rn(v.x, v.y);
    d[1] = __floats2half2_rn(v.z, v.w);
}

// ---------------- softmax over heads ----------------
__global__ __launch_bounds__(256) void softmax_heads(
    const float* __restrict__ partial, float* __restrict__ weight,
    float* __restrict__ wmap_out)
{
    int n = blockIdx.x * 256 + threadIdx.x;
    float s[NHEADS] = {0.f, 0.f, 0.f, 0.f};
    #pragma unroll
    for (int h = 0; h < NHEADS; h++)
        #pragma unroll
        for (int j = 0; j < NSCHUNK; j++)
            s[h] += partial[((size_t)(h * NSCHUNK + j)) * N_DIM + n];
    const float inv_sqrt_dk = 1.0f / 32.0f;
    float m = -1e30f;
    #pragma unroll
    for (int h = 0; h < NHEADS; h++) { s[h] *= inv_sqrt_dk; m = fmaxf(m, s[h]); }
    float e[NHEADS], sum = 0.f;
    #pragma unroll
    for (int h = 0; h < NHEADS; h++) { e[h] = __expf(s[h] - m); sum += e[h]; }
    float inv = 1.0f / sum;
    #pragma unroll
    for (int h = 0; h < NHEADS; h++) {
        float wv = e[h] * inv;
        weight[(size_t)h * N_DIM + n]   = wv;
        wmap_out[(size_t)h * N_DIM + n] = wv;
    }
}

// ---------------- z + residual + LayerNorm (fp16 keys in, fp16 fused out [k,n]) -------
__global__ __launch_bounds__(512) void z_layernorm(
    const __half* __restrict__ keysh, const float* __restrict__ q,
    const float* __restrict__ weight, const float* __restrict__ gamma,
    const float* __restrict__ beta, __half* __restrict__ fusedh)
{
    const int c = blockIdx.x;
    __shared__ float r1[16], r2[16];
    __shared__ float s_mean, s_rstd;

    float v[2][4];
    float lsum = 0.f, lsq = 0.f;
    #pragma unroll
    for (int j = 0; j < 2; j++) {
        const int n4 = (j * 512 + threadIdx.x) * 4;
        float4 qa = *reinterpret_cast<const float4*>(&q[(size_t)c * N_DIM + n4]);
        v[j][0] = qa.x; v[j][1] = qa.y; v[j][2] = qa.z; v[j][3] = qa.w;
        #pragma unroll
        for (int h = 0; h < NHEADS; h++) {
            const __half2* kh = reinterpret_cast<const __half2*>(
                &keysh[((size_t)(h * L_DIM + c)) * N_DIM + n4]);
            float2 ka = __half22float2(kh[0]);
            float2 kb = __half22float2(kh[1]);
            float4 wv = *reinterpret_cast<const float4*>(&weight[(size_t)h * N_DIM + n4]);
            v[j][0] += wv.x * ka.x; v[j][1] += wv.y * ka.y;
            v[j][2] += wv.z * kb.x; v[j][3] += wv.w * kb.y;
        }
        #pragma unroll
        for (int e = 0; e < 4; e++) { lsum += v[j][e]; lsq += v[j][e] * v[j][e]; }
    }
    #pragma unroll
    for (int o = 16; o > 0; o >>= 1) {
        lsum += __shfl_xor_sync(0xffffffffu, lsum, o);
        lsq  += __shfl_xor_sync(0xffffffffu, lsq, o);
    }
    const int wid = threadIdx.x >> 5, lid = threadIdx.x & 31;
    if (lid == 0) { r1[wid] = lsum; r2[wid] = lsq; }
    __syncthreads();
    if (threadIdx.x == 0) {
        float ts = 0.f, tq = 0.f;
        #pragma unroll
        for (int i = 0; i < 16; i++) { ts += r1[i]; tq += r2[i]; }
        float mean = ts * (1.0f / N_DIM);
        float var  = tq * (1.0f / N_DIM) - mean * mean;
        s_mean = mean;
        s_rstd = rsqrtf(var + 1e-5f);
    }
    __syncthreads();
    const float mean = s_mean, rstd = s_rstd;
    #pragma unroll
    for (int j = 0; j < 2; j++) {
        const int n4 = (j * 512 + threadIdx.x) * 4;
        float4 ga = *reinterpret_cast<const float4*>(&gamma[n4]);
        float4 ba = *reinterpret_cast<const float4*>(&beta[n4]);
        float o0 = (v[j][0] - mean) * rstd * ga.x + ba.x;
        float o1 = (v[j][1] - mean) * rstd * ga.y + ba.y;
        float o2 = (v[j][2] - mean) * rstd * ga.z + ba.z;
        float o3 = (v[j][3] - mean) * rstd * ga.w + ba.w;
        __half2* dst = reinterpret_cast<__half2*>(&fusedh[(size_t)c * N_DIM + n4]);
        dst[0] = __floats2half2_rn(o0, o1);
        dst[1] = __floats2half2_rn(o2, o3);
    }
}

// ---------------- launch ----------------
extern "C" void kernel_launch(void* const* d_in, const int* in_sizes, int n_in,
                              void* d_out, int out_size)
{
    const float* point = (const float*)d_in[0];
    const float* img   = (const float*)d_in[1];
    const float* W_img = (const float*)d_in[2];
    const float* b_img = (const float*)d_in[3];
    const float* W_L   = (const float*)d_in[4];
    const float* b_L   = (const float*)d_in[5];
    const float* ln_g  = (const float*)d_in[6];
    const float* ln_b  = (const float*)d_in[7];
    const float* W_f   = (const float*)d_in[8];
    const float* b_f   = (const float*)d_in[9];

    float* out  = (float*)d_out;
    float* wmap = out + (size_t)L_DIM * N_DIM;

    float *q, *partial, *weight;
    __half *keysh, *fusedh;
    cudaGetSymbolAddress((void**)&q,       g_q);
    cudaGetSymbolAddress((void**)&keysh,   g_keysh);
    cudaGetSymbolAddress((void**)&partial, g_partial);
    cudaGetSymbolAddress((void**)&weight,  g_weight);
    cudaGetSymbolAddress((void**)&fusedh,  g_fusedh);

    __half *WL, *WI, *WF, *P16, *I16;
    cudaGetSymbolAddress((void**)&WL, g_WL);
    cudaGetSymbolAddress((void**)&WI, g_Wimg);
    cudaGetSymbolAddress((void**)&WF, g_Wf);
    cudaGetSymbolAddress((void**)&P16, g_P16);
    cudaGetSymbolAddress((void**)&I16, g_I16);

    cudaFuncSetAttribute(gemm_q,    cudaFuncAttributeMaxDynamicSharedMemorySize, GEMM_DSMEM);
    cudaFuncSetAttribute(gemm_keys, cudaFuncAttributeMaxDynamicSharedMemorySize, GEMM_DSMEM);
    cudaFuncSetAttribute(gemm_f,    cudaFuncAttributeMaxDynamicSharedMemorySize, GEMM_DSMEM);

    convert_w<<<(6 * L_DIM * K_DIM) / 512, 256>>>(W_L, W_img, W_f, WL, WI, WF);
    convert_act<<<dim3((K_DIM * N_DIM) / 1024, 2), 256>>>(point, P16, img, I16);

    gemm_q<<<dim3(N_DIM / GBN, L_DIM / GBM), 256, GEMM_DSMEM>>>(WL, P16, b_L, q);
    gemm_keys<<<dim3(N_DIM / GBN, (NHEADS * L_DIM) / GBM), 256, GEMM_DSMEM>>>(
        WI, I16, b_img, keysh, q, partial);

    softmax_heads<<<N_DIM / 256, 256>>>(partial, weight, wmap);
    z_layernorm<<<L_DIM, 512>>>(keysh, q, weight, ln_g, ln_b, fusedh);

    gemm_f<<<dim3(N_DIM / GBN, L_DIM / GBM), 256, GEMM_DSMEM>>>(WF, fusedh, b_f, out);
}

// round 15
// speedup vs baseline: 1.2445x; 1.0475x over previous
#include <cuda_runtime.h>
#include <cuda_fp16.h>
#include <cstdint>

#define L_DIM 1024
#define N_DIM 4096
#define K_DIM 1024
#define NHEADS 4
#define NSCHUNK 8

// ---------------- scratch (device globals; no allocs allowed) ----------------
__device__ __half g_qh[L_DIM * N_DIM];                  // fp16 q [c,n]
__device__ __half g_keysh[NHEADS * L_DIM * N_DIM];
__device__ float  g_partial[NHEADS * NSCHUNK * N_DIM];
__device__ float  g_weight[NHEADS * N_DIM];
__device__ __half g_fusedh[L_DIM * N_DIM];              // fp16 LN out [k,n]

__device__ __half g_WL[L_DIM * K_DIM];
__device__ __half g_Wimg[NHEADS * L_DIM * K_DIM];
__device__ __half g_Wf[L_DIM * K_DIM];
__device__ __half g_P16[K_DIM * N_DIM];
__device__ __half g_I16[K_DIM * N_DIM];

// ---------------- PTX helpers (sm_80-portable only) ----------------
__device__ __forceinline__ uint32_t smem_u32(const void* p) {
    uint32_t r;
    asm("{ .reg .u64 t; cvta.to.shared.u64 t, %1; cvt.u32.u64 %0, t; }" : "=r"(r) : "l"(p));
    return r;
}
__device__ __forceinline__ void cp16(uint32_t dst, const void* src) {
    asm volatile("cp.async.cg.shared.global [%0], [%1], 16;" :: "r"(dst), "l"(src) : "memory");
}
__device__ __forceinline__ void cp_commit() {
    asm volatile("cp.async.commit_group;" ::: "memory");
}
__device__ __forceinline__ void cp_wait1() {
    asm volatile("cp.async.wait_group 1;" ::: "memory");
}
__device__ __forceinline__ void cp_wait0() {
    asm volatile("cp.async.wait_group 0;" ::: "memory");
}
__device__ __forceinline__ void ldsm_x4(uint32_t& r0, uint32_t& r1, uint32_t& r2, uint32_t& r3,
                                        uint32_t addr) {
    asm volatile("ldmatrix.sync.aligned.m8n8.x4.shared.b16 {%0,%1,%2,%3}, [%4];"
                 : "=r"(r0), "=r"(r1), "=r"(r2), "=r"(r3) : "r"(addr));
}
__device__ __forceinline__ void ldsm_x4_trans(uint32_t& r0, uint32_t& r1, uint32_t& r2, uint32_t& r3,
                                              uint32_t addr) {
    asm volatile("ldmatrix.sync.aligned.m8n8.x4.trans.shared.b16 {%0,%1,%2,%3}, [%4];"
                 : "=r"(r0), "=r"(r1), "=r"(r2), "=r"(r3) : "r"(addr));
}
__device__ __forceinline__ void mma_f16(float* c, const uint32_t* a, uint32_t b0, uint32_t b1) {
    asm volatile(
        "mma.sync.aligned.m16n8k16.row.col.f32.f16.f16.f32 "
        "{%0,%1,%2,%3}, {%4,%5,%6,%7}, {%8,%9}, {%0,%1,%2,%3};"
        : "+f"(c[0]), "+f"(c[1]), "+f"(c[2]), "+f"(c[3])
        : "r"(a[0]), "r"(a[1]), "r"(a[2]), "r"(a[3]), "r"(b0), "r"(b1));
}

// ---------------- fp16 mma.sync GEMM: A [m,k] k-major, B [k,n] n-major (ldsm.trans) ----
#define GBM 128
#define GBN 128
#define GBK 64
#define OFF_A 0
#define OFF_B 16384
#define STAGE_B 32768
#define NSTAGE 3
#define GEMM_DSMEM (NSTAGE * STAGE_B)   // 96 KB -> 2 CTAs/SM
#define KSTAGES (K_DIM / GBK)           // 16

template <bool SCORE, typename OT>
__device__ __forceinline__ void gemm_body(
    const __half* __restrict__ A, const __half* __restrict__ B,
    const float* __restrict__ bias, OT* __restrict__ C,
    int bm, int bn,
    const __half* __restrict__ qbuf, float* __restrict__ partial, int chunk_idx)
{
    extern __shared__ char sm_raw[];
    const uint32_t sbase = smem_u32(sm_raw);

    const int tid  = threadIdx.x;
    const int lane = tid & 31;
    const int wid  = tid >> 5;
    const int wm   = wid >> 1;
    const int wn   = wid & 1;

    int arow[4], acol[4], brow[4], bcol[4];
    uint32_t adst[4], bdst[4];
    #pragma unroll
    for (int t = 0; t < 4; t++) {
        int idx = (t << 8) + tid;
        int ra = idx >> 3, ca = idx & 7;
        arow[t] = ra; acol[t] = ca;
        adst[t] = (uint32_t)((ra << 7) + ((ca ^ (ra & 7)) << 4));
        int rb = idx >> 4, cb = idx & 15;
        brow[t] = rb; bcol[t] = cb;
        bdst[t] = (uint32_t)((rb << 8) + ((cb ^ (rb & 7)) << 4));
    }

    auto issue_stage = [&](int kstage, int buf) {
        const uint32_t sb = sbase + buf * STAGE_B;
        const int k0 = kstage * GBK;
        #pragma unroll
        for (int t = 0; t < 4; t++) {
            cp16(sb + OFF_A + adst[t],
                 A + (size_t)(bm + arow[t]) * K_DIM + k0 + (acol[t] << 3));
            cp16(sb + OFF_B + bdst[t],
                 B + (size_t)(k0 + brow[t]) * N_DIM + bn + (bcol[t] << 3));
        }
    };

    float acc[2][8][4];
    #pragma unroll
    for (int m = 0; m < 2; m++)
        #pragma unroll
        for (int n = 0; n < 8; n++)
            #pragma unroll
            for (int v = 0; v < 4; v++)
                acc[m][n][v] = 0.0f;

    const int a_row0 = wm * 32 + (lane & 15);
    const int a_ch0  = lane >> 4;
    const int b_krow0 = (lane & 7) + (((lane >> 3) & 1) << 3);
    const int b_nch0  = wn * 8 + (lane >> 4);

    issue_stage(0, 0); cp_commit();
    issue_stage(1, 1); cp_commit();

    int bc = 0;
    for (int i = 0; i < KSTAGES; i++) {
        if (i < KSTAGES - 1) cp_wait1(); else cp_wait0();
        __syncthreads();

        if (i + 2 < KSTAGES) {
            int bi = bc + 2; if (bi >= NSTAGE) bi -= NSTAGE;
            issue_stage(i + 2, bi);
            cp_commit();
        }

        const uint32_t st = sbase + bc * STAGE_B;
        #pragma unroll
        for (int ks = 0; ks < 4; ks++) {
            uint32_t ah[2][4], bh[4][4];
            #pragma unroll
            for (int mt = 0; mt < 2; mt++) {
                const int r = a_row0 + mt * 16;
                const int ch = ks * 2 + a_ch0;
                ldsm_x4(ah[mt][0], ah[mt][1], ah[mt][2], ah[mt][3],
                        st + OFF_A + (r << 7) + ((ch ^ (r & 7)) << 4));
            }
            #pragma unroll
            for (int np = 0; np < 4; np++) {
                const int r = ks * 16 + b_krow0;
                const int nc = b_nch0 + np * 2;
                ldsm_x4_trans(bh[np][0], bh[np][1], bh[np][2], bh[np][3],
                              st + OFF_B + (r << 8) + ((nc ^ (r & 7)) << 4));
            }
            #pragma unroll
            for (int mt = 0; mt < 2; mt++)
                #pragma unroll
                for (int np = 0; np < 4; np++) {
                    mma_f16(acc[mt][np * 2 + 0], ah[mt], bh[np][0], bh[np][1]);
                    mma_f16(acc[mt][np * 2 + 1], ah[mt], bh[np][2], bh[np][3]);
                }
        }
        bc = (bc + 1 == NSTAGE) ? 0 : bc + 1;
    }

    float s[16];
    if (SCORE) {
        #pragma unroll
        for (int j = 0; j < 16; j++) s[j] = 0.0f;
    }

    #pragma unroll
    for (int mt = 0; mt < 2; mt++) {
        const int row = bm + wm * 32 + mt * 16 + (lane >> 2);
        const float bv0 = bias[row], bv8 = bias[row + 8];
        const int c0 = row & (L_DIM - 1);
        #pragma unroll
        for (int nt = 0; nt < 8; nt++) {
            const int col = bn + wn * 64 + nt * 8 + (lane & 3) * 2;
            const float k00 = acc[mt][nt][0] + bv0, k01 = acc[mt][nt][1] + bv0;
            const float k80 = acc[mt][nt][2] + bv8, k81 = acc[mt][nt][3] + bv8;
            if (sizeof(OT) == 2) {
                *reinterpret_cast<__half2*>(
                    (__half*)C + (size_t)row * N_DIM + col) = __floats2half2_rn(k00, k01);
                *reinterpret_cast<__half2*>(
                    (__half*)C + (size_t)(row + 8) * N_DIM + col) = __floats2half2_rn(k80, k81);
            } else {
                *reinterpret_cast<float2*>(
                    (float*)C + (size_t)row * N_DIM + col) = make_float2(k00, k01);
                *reinterpret_cast<float2*>(
                    (float*)C + (size_t)(row + 8) * N_DIM + col) = make_float2(k80, k81);
            }
            if (SCORE) {
                const float2 q0 = __half22float2(*reinterpret_cast<const __half2*>(
                    &qbuf[(size_t)c0 * N_DIM + col]));
                const float2 q8 = __half22float2(*reinterpret_cast<const __half2*>(
                    &qbuf[(size_t)(c0 + 8) * N_DIM + col]));
                s[nt * 2 + 0] += k00 * q0.x + k80 * q8.x;
                s[nt * 2 + 1] += k01 * q0.y + k81 * q8.y;
            }
        }
    }

    if (SCORE) {
        #pragma unroll
        for (int j = 0; j < 16; j++) {
            s[j] += __shfl_xor_sync(0xffffffffu, s[j], 4);
            s[j] += __shfl_xor_sync(0xffffffffu, s[j], 8);
            s[j] += __shfl_xor_sync(0xffffffffu, s[j], 16);
        }
        __syncthreads();
        float* sbuf = reinterpret_cast<float*>(sm_raw);
        if ((lane >> 2) == 0) {
            #pragma unroll
            for (int nt = 0; nt < 8; nt++) {
                const int lc = wn * 64 + nt * 8 + (lane & 3) * 2;
                sbuf[wid * 128 + lc + 0] = s[nt * 2 + 0];
                sbuf[wid * 128 + lc + 1] = s[nt * 2 + 1];
            }
        }
        __syncthreads();
        if (tid < 128) {
            const int wn_ = tid >> 6;
            float tot = sbuf[(0 * 2 + wn_) * 128 + tid]
                      + sbuf[(1 * 2 + wn_) * 128 + tid]
                      + sbuf[(2 * 2 + wn_) * 128 + tid]
                      + sbuf[(3 * 2 + wn_) * 128 + tid];
            partial[(size_t)chunk_idx * N_DIM + bn + tid] = tot;
        }
    }
}

__global__ __launch_bounds__(256, 2) void gemm_q(
    const __half* __restrict__ WL, const __half* __restrict__ P16,
    const float* __restrict__ b_L, __half* __restrict__ qh)
{
    gemm_body<false, __half>(WL, P16, b_L, qh, blockIdx.y * GBM, blockIdx.x * GBN,
                             nullptr, nullptr, 0);
}

__global__ __launch_bounds__(256, 2) void gemm_keys(
    const __half* __restrict__ WI, const __half* __restrict__ I16,
    const float* __restrict__ b_img, __half* __restrict__ keysh,
    const __half* __restrict__ qh, float* __restrict__ partial)
{
    gemm_body<true, __half>(WI, I16, b_img, keysh, blockIdx.y * GBM, blockIdx.x * GBN,
                            qh, partial, blockIdx.y);
}

__global__ __launch_bounds__(256, 2) void gemm_f(
    const __half* __restrict__ WF, const __half* __restrict__ F16,
    const float* __restrict__ bias, float* __restrict__ C)
{
    gemm_body<false, float>(WF, F16, bias, C, blockIdx.y * GBM, blockIdx.x * GBN,
                            nullptr, nullptr, 0);
}

// ---------------- single fused fp32->fp16 convert (weights + activations) -------------
// ranges in float4 units: WL 1M, WI 4M, WF 1M, P 4M, I 4M elements
__global__ __launch_bounds__(256) void convert_all(
    const float* __restrict__ W_L, const float* __restrict__ W_img,
    const float* __restrict__ W_f, const float* __restrict__ point,
    const float* __restrict__ img,
    __half* __restrict__ WL, __half* __restrict__ WI, __half* __restrict__ WF,
    __half* __restrict__ P16, __half* __restrict__ I16)
{
    const size_t WSZ = (size_t)L_DIM * K_DIM;          // 1M
    const size_t ASZ = (size_t)K_DIM * N_DIM;          // 4M
    size_t i = ((size_t)blockIdx.x * 256 + threadIdx.x) * 4;
    const float* src; __half* dst; size_t off;
    if (i < WSZ)                    { src = W_L;   dst = WL;  off = i; }
    else if (i < 5 * WSZ)           { src = W_img; dst = WI;  off = i - WSZ; }
    else if (i < 6 * WSZ)           { src = W_f;   dst = WF;  off = i - 5 * WSZ; }
    else if (i < 6 * WSZ + ASZ)     { src = point; dst = P16; off = i - 6 * WSZ; }
    else                            { src = img;   dst = I16; off = i - 6 * WSZ - ASZ; }
    float4 v = *reinterpret_cast<const float4*>(src + off);
    __half2* d = reinterpret_cast<__half2*>(dst + off);
    d[0] = __floats2half2_rn(v.x, v.y);
    d[1] = __floats2half2_rn(v.z, v.w);
}

// ---------------- softmax over heads ----------------
__global__ __launch_bounds__(256) void softmax_heads(
    const float* __restrict__ partial, float* __restrict__ weight,
    float* __restrict__ wmap_out)
{
    int n = blockIdx.x * 256 + threadIdx.x;
    float s[NHEADS] = {0.f, 0.f, 0.f, 0.f};
    #pragma unroll
    for (int h = 0; h < NHEADS; h++)
        #pragma unroll
        for (int j = 0; j < NSCHUNK; j++)
            s[h] += partial[((size_t)(h * NSCHUNK + j)) * N_DIM + n];
    const float inv_sqrt_dk = 1.0f / 32.0f;
    float m = -1e30f;
    #pragma unroll
    for (int h = 0; h < NHEADS; h++) { s[h] *= inv_sqrt_dk; m = fmaxf(m, s[h]); }
    float e[NHEADS], sum = 0.f;
    #pragma unroll
    for (int h = 0; h < NHEADS; h++) { e[h] = __expf(s[h] - m); sum += e[h]; }
    float inv = 1.0f / sum;
    #pragma unroll
    for (int h = 0; h < NHEADS; h++) {
        float wv = e[h] * inv;
        weight[(size_t)h * N_DIM + n]   = wv;
        wmap_out[(size_t)h * N_DIM + n] = wv;
    }
}

// ---------------- z + residual + LayerNorm (all-fp16 in, fp16 out [k,n]) --------------
__global__ __launch_bounds__(512) void z_layernorm(
    const __half* __restrict__ keysh, const __half* __restrict__ qh,
    const float* __restrict__ weight, const float* __restrict__ gamma,
    const float* __restrict__ beta, __half* __restrict__ fusedh)
{
    const int c = blockIdx.x;
    __shared__ float r1[16], r2[16];
    __shared__ float s_mean, s_rstd;

    float v[2][4];
    float lsum = 0.f, lsq = 0.f;
    #pragma unroll
    for (int j = 0; j < 2; j++) {
        const int n4 = (j * 512 + threadIdx.x) * 4;
        const __half2* qa = reinterpret_cast<const __half2*>(&qh[(size_t)c * N_DIM + n4]);
        float2 q0 = __half22float2(qa[0]);
        float2 q1 = __half22float2(qa[1]);
        v[j][0] = q0.x; v[j][1] = q0.y; v[j][2] = q1.x; v[j][3] = q1.y;
        #pragma unroll
        for (int h = 0; h < NHEADS; h++) {
            const __half2* kh = reinterpret_cast<const __half2*>(
                &keysh[((size_t)(h * L_DIM + c)) * N_DIM + n4]);
            float2 ka = __half22float2(kh[0]);
            float2 kb = __half22float2(kh[1]);
            float4 wv = *reinterpret_cast<const float4*>(&weight[(size_t)h * N_DIM + n4]);
            v[j][0] += wv.x * ka.x; v[j][1] += wv.y * ka.y;
            v[j][2] += wv.z * kb.x; v[j][3] += wv.w * kb.y;
        }
        #pragma unroll
        for (int e = 0; e < 4; e++) { lsum += v[j][e]; lsq += v[j][e] * v[j][e]; }
    }
    #pragma unroll
    for (int o = 16; o > 0; o >>= 1) {
        lsum += __shfl_xor_sync(0xffffffffu, lsum, o);
        lsq  += __shfl_xor_sync(0xffffffffu, lsq, o);
    }
    const int wid = threadIdx.x >> 5, lid = threadIdx.x & 31;
    if (lid == 0) { r1[wid] = lsum; r2[wid] = lsq; }
    __syncthreads();
    if (threadIdx.x == 0) {
        float ts = 0.f, tq = 0.f;
        #pragma unroll
        for (int i = 0; i < 16; i++) { ts += r1[i]; tq += r2[i]; }
        float mean = ts * (1.0f / N_DIM);
        float var  = tq * (1.0f / N_DIM) - mean * mean;
        s_mean = mean;
        s_rstd = rsqrtf(var + 1e-5f);
    }
    __syncthreads();
    const float mean = s_mean, rstd = s_rstd;
    #pragma unroll
    for (int j = 0; j < 2; j++) {
        const int n4 = (j * 512 + threadIdx.x) * 4;
        float4 ga = *reinterpret_cast<const float4*>(&gamma[n4]);
        float4 ba = *reinterpret_cast<const float4*>(&beta[n4]);
        float o0 = (v[j][0] - mean) * rstd * ga.x + ba.x;
        float o1 = (v[j][1] - mean) * rstd * ga.y + ba.y;
        float o2 = (v[j][2] - mean) * rstd * ga.z + ba.z;
        float o3 = (v[j][3] - mean) * rstd * ga.w + ba.w;
        __half2* dst = reinterpret_cast<__half2*>(&fusedh[(size_t)c * N_DIM + n4]);
        dst[0] = __floats2half2_rn(o0, o1);
        dst[1] = __floats2half2_rn(o2, o3);
    }
}

// ---------------- launch ----------------
extern "C" void kernel_launch(void* const* d_in, const int* in_sizes, int n_in,
                              void* d_out, int out_size)
{
    const float* point = (const float*)d_in[0];
    const float* img   = (const float*)d_in[1];
    const float* W_img = (const float*)d_in[2];
    const float* b_img = (const float*)d_in[3];
    const float* W_L   = (const float*)d_in[4];
    const float* b_L   = (const float*)d_in[5];
    const float* ln_g  = (const float*)d_in[6];
    const float* ln_b  = (const float*)d_in[7];
    const float* W_f   = (const float*)d_in[8];
    const float* b_f   = (const float*)d_in[9];

    float* out  = (float*)d_out;
    float* wmap = out + (size_t)L_DIM * N_DIM;

    float *partial, *weight;
    __half *qh, *keysh, *fusedh;
    cudaGetSymbolAddress((void**)&qh,      g_qh);
    cudaGetSymbolAddress((void**)&keysh,   g_keysh);
    cudaGetSymbolAddress((void**)&partial, g_partial);
    cudaGetSymbolAddress((void**)&weight,  g_weight);
    cudaGetSymbolAddress((void**)&fusedh,  g_fusedh);

    __half *WL, *WI, *WF, *P16, *I16;
    cudaGetSymbolAddress((void**)&WL, g_WL);
    cudaGetSymbolAddress((void**)&WI, g_Wimg);
    cudaGetSymbolAddress((void**)&WF, g_Wf);
    cudaGetSymbolAddress((void**)&P16, g_P16);
    cudaGetSymbolAddress((void**)&I16, g_I16);

    cudaFuncSetAttribute(gemm_q,    cudaFuncAttributeMaxDynamicSharedMemorySize, GEMM_DSMEM);
    cudaFuncSetAttribute(gemm_keys, cudaFuncAttributeMaxDynamicSharedMemorySize, GEMM_DSMEM);
    cudaFuncSetAttribute(gemm_f,    cudaFuncAttributeMaxDynamicSharedMemorySize, GEMM_DSMEM);

    // 14M elements total, 4 per thread
    convert_all<<<(14 * 1024 * 1024) / 1024, 256>>>(
        W_L, W_img, W_f, point, img, WL, WI, WF, P16, I16);

    gemm_q<<<dim3(N_DIM / GBN, L_DIM / GBM), 256, GEMM_DSMEM>>>(WL, P16, b_L, qh);
    gemm_keys<<<dim3(N_DIM / GBN, (NHEADS * L_DIM) / GBM), 256, GEMM_DSMEM>>>(
        WI, I16, b_img, keysh, qh, partial);

    softmax_heads<<<N_DIM / 256, 256>>>(partial, weight, wmap);
    z_layernorm<<<L_DIM, 512>>>(keysh, qh, weight, ln_g, ln_b, fusedh);

    gemm_f<<<dim3(N_DIM / GBN, L_DIM / GBM), 256, GEMM_DSMEM>>>(WF, fusedh, b_f, out);
}